// round 9
// baseline (speedup 1.0000x reference)
#include <cuda_runtime.h>
#include <cstdint>

#define NB 16
#define NN 4096
#define NC 64
#define NP 1024
#define NSAMP 32
#define MT (NB*NP*NSAMP)          // 524288 rows
#define OUT_FEAT_OFF (NB*NP*3)    // 49152

// ---------------- scratch (__device__ globals; no allocations) ----------------
// 16B alignment on everything touched by float4 / b64 vector accesses.
__device__ __align__(16) float  g_featT[NB*NN*NC];   // (B,N,C) features, 16.8MB
__device__             int      g_ball[NB*NP*NSAMP]; // ball query indices
__device__ __align__(16) float  g_x1[MT*64];         // raw layer1 out, 134MB
__device__ __align__(16) float  g_x2[MT*64];         // raw layer2 out, 134MB
__device__ __align__(16) float  g_mx[NB*NP*128];     // raw layer3 max over s
__device__ __align__(16) float  g_mn[NB*NP*128];     // raw layer3 min over s
__device__ __align__(16) float  g_Wt1[67*64];
__device__ __align__(16) float  g_Wt2[64*64];
__device__ __align__(16) float  g_Wt3[64*128];
__device__ double g_s1[64], g_q1[64], g_s2[64], g_q2[64], g_s3[128], g_q3[128];
__device__ float  g_sc1[64], g_sh1[64], g_sc2[64], g_sh2[64], g_sc3[128], g_sh3[128];

// monotonic float<->uint encoding (for atomic max/min on possibly-negative floats)
__device__ __forceinline__ unsigned fenc(float f) {
    unsigned u = __float_as_uint(f);
    return (u & 0x80000000u) ? ~u : (u | 0x80000000u);
}
__device__ __forceinline__ float fdec(unsigned u) {
    u = (u & 0x80000000u) ? (u & 0x7fffffffu) : ~u;
    return __uint_as_float(u);
}

// squared distance with NO fma contraction, left-associated like XLA:
// (dx*dx + dy*dy) + dz*dz
__device__ __forceinline__ float dist2_xla(float dx, float dy, float dz) {
    return __fadd_rn(__fadd_rn(__fmul_rn(dx, dx), __fmul_rn(dy, dy)),
                     __fmul_rn(dz, dz));
}

// ---------------- packed f32x2 helpers (FFMA2 path, sm_103a) ----------------
__device__ __forceinline__ void ffma2(unsigned long long& d,
                                      unsigned long long a,
                                      unsigned long long b) {
    asm("fma.rn.f32x2 %0, %1, %2, %0;" : "+l"(d) : "l"(a), "l"(b));
}
__device__ __forceinline__ unsigned long long dup2(float x) {
    unsigned u = __float_as_uint(x);
    unsigned long long r;
    asm("mov.b64 %0, {%1, %1};" : "=l"(r) : "r"(u));
    return r;
}
__device__ __forceinline__ void unpack2(unsigned long long v, float& lo, float& hi) {
    unsigned a, b;
    asm("mov.b64 {%0, %1}, %2;" : "=r"(a), "=r"(b) : "l"(v));
    lo = __uint_as_float(a); hi = __uint_as_float(b);
}

// ---------------- prep: zero accumulators + transpose weights ----------------
__global__ void prep_kernel(const float* __restrict__ W1,
                            const float* __restrict__ W2,
                            const float* __restrict__ W3) {
    int t = threadIdx.x;
    for (int i = t; i < 64; i += 256) { g_s1[i]=0.0; g_q1[i]=0.0; g_s2[i]=0.0; g_q2[i]=0.0; }
    for (int i = t; i < 128; i += 256) { g_s3[i]=0.0; g_q3[i]=0.0; }
    for (int i = t; i < 64*67; i += 256) { int o = i/67, c = i - o*67; g_Wt1[c*64 + o] = W1[i]; }
    for (int i = t; i < 64*64; i += 256) { int o = i>>6, c = i&63;    g_Wt2[c*64 + o] = W2[i]; }
    for (int i = t; i < 128*64; i += 256){ int o = i>>6, c = i&63;    g_Wt3[c*128 + o] = W3[i]; }
}

// ---------------- transpose features (B,C,N) -> (B,N,C) ----------------
__global__ void featT_kernel(const float* __restrict__ f) {
    __shared__ float t[32][33];
    int b = blockIdx.z, j0 = blockIdx.x*32, c0 = blockIdx.y*32;
    int tx = threadIdx.x, ty = threadIdx.y;
    for (int k = ty; k < 32; k += 8)
        t[k][tx] = f[b*(NC*NN) + (c0+k)*NN + j0 + tx];
    __syncthreads();
    for (int k = ty; k < 32; k += 8)
        g_featT[(b*NN + j0 + k)*NC + c0 + tx] = t[tx][k];
}

// ---------------- FPS: one block per batch, ONE barrier per iteration ----------------
// NO dynamic smem (previous rounds requested 48KB dynamic + 24B static = over
// the no-opt-in cap -> launch failed -> graph capture invalidated).
// Winner coords are re-read from global xyz via broadcast __ldg (L1-hit).
// Warp argmax via two u32 REDUX ops; packed atomicMax keeps exact tie-break.
__global__ __launch_bounds__(1024) void fps_kernel(const float* __restrict__ xyz,
                                                   float* __restrict__ out) {
    __shared__ unsigned long long s_best[3];

    int b = blockIdx.x, tid = threadIdx.x;
    int lane = tid & 31;
    const float* X = xyz + b*NN*3;

    float px[4], py[4], pz[4], dist[4];
#pragma unroll
    for (int k = 0; k < 4; k++) {
        int j = tid + k*1024;
        px[k] = X[j*3+0]; py[k] = X[j*3+1]; pz[k] = X[j*3+2];
        dist[k] = 1e10f;
    }
    if (tid < 3) s_best[tid] = 0ull;
    __syncthreads();

    int cur = 0;
    float* outB = out + b*NP*3;
    for (int i = 0; i < NP; i++) {
        // broadcast read of current point's coords (all lanes same address, L1)
        float lx = __ldg(&X[cur*3+0]);
        float ly = __ldg(&X[cur*3+1]);
        float lz = __ldg(&X[cur*3+2]);
        if (tid == 0) { outB[i*3+0] = lx; outB[i*3+1] = ly; outB[i*3+2] = lz; }

        // thread-local best among 4 points (max dist, then lowest index)
        unsigned long long best = 0ull;
#pragma unroll
        for (int k = 0; k < 4; k++) {
            float d = dist2_xla(px[k]-lx, py[k]-ly, pz[k]-lz);
            d = fminf(dist[k], d);
            dist[k] = d;
            unsigned long long key =
                (((unsigned long long)__float_as_uint(d)) << 32) |
                (unsigned)(4095 - (tid + k*1024));
            best = (key > best) ? key : best;
        }
        // warp reduction: two u32 REDUX ops
        unsigned d32  = (unsigned)(best >> 32);
        unsigned m    = __reduce_max_sync(0xffffffffu, d32);
        unsigned ridx = (d32 == m) ? (unsigned)(best & 0xffffffffu) : 0u;
        unsigned rmax = __reduce_max_sync(0xffffffffu, ridx);

        int slot = i % 3;
        if (lane == 0)
            atomicMax(&s_best[slot], (((unsigned long long)m) << 32) | rmax);
        __syncthreads();
        cur = 4095 - (int)(unsigned)(s_best[slot] & 0xffffffffu);
        if (tid == 0) s_best[(i + 2) % 3] = 0ull;   // == slot of iter i-1
    }
}

// ---------------- ball query: warp per center ----------------
__global__ __launch_bounds__(256) void ball_kernel(const float* __restrict__ xyz,
                                                   const float* __restrict__ newxyz) {
    int w = blockIdx.x*8 + (threadIdx.x >> 5);
    int lane = threadIdx.x & 31;
    int b = w >> 10, p = w & 1023;
    const float* X = xyz + b*NN*3;
    const float* c = newxyz + (size_t)(b*NP + p)*3;
    float cx = c[0], cy = c[1], cz = c[2];
    int* dst = g_ball + (size_t)(b*NP + p)*NSAMP;
    const float RR = 0.04f;   // float32(0.2*0.2)

    int cnt = 0, first = -1;
    for (int j0 = 0; j0 < NN && cnt < NSAMP; j0 += 32) {
        int j = j0 + lane;
        float d = dist2_xla(X[j*3+0]-cx, X[j*3+1]-cy, X[j*3+2]-cz);
        bool val = d < RR;
        unsigned m = __ballot_sync(0xffffffffu, val);
        if (m) {
            if (first < 0) first = __shfl_sync(0xffffffffu, j, __ffs(m)-1);
            if (val) {
                int pos = cnt + __popc(m & ((1u << lane) - 1u));
                if (pos < NSAMP) dst[pos] = j;
            }
            cnt += __popc(m);
            if (cnt > NSAMP) cnt = NSAMP;
        }
    }
    if (lane >= cnt) dst[lane] = first;
}

// A tile is stored K-major: As_T[k*130 + r], r = 0..127, k = channel.
// Stride 130 (even) keeps 8B alignment for ld.shared.b64 row-pair loads.
// B (weights) read straight from L1-resident __device__ globals.
#define ATS 130

// ---------------- GEMM1: gather + (B,P,S,67) @ W1^T -> x1, stats ----------------
__global__ __launch_bounds__(256) void gemm1_kernel(const float* __restrict__ xyz,
                                                    const float* __restrict__ newxyz) {
    extern __shared__ char smraw[];
    float*  AsT  = (float*)smraw;                       // 67 x 130 (+2 pad)
    double* ssum = (double*)(AsT + 67*ATS + 2);         // 64 (byte 34848, 8-al)
    double* ssq  = ssum + 64;                           // 64
    int*    s_j  = (int*)(ssq + 64);                    // 128
    float*  s_cn = (float*)(s_j + 128);                 // 12

    int tid = threadIdx.x;
    int m0 = blockIdx.x * 128;
    int b  = m0 >> 15;
    const float* Xb = xyz + b*NN*3;

    if (tid < 64) { ssum[tid] = 0.0; ssq[tid] = 0.0; }
    for (int r = tid; r < 128; r += 256) {
        int m = m0 + r; int p = (m & 32767) >> 5; int s = m & 31;
        s_j[r] = g_ball[(((b<<10) + p) << 5) + s];
    }
    if (tid < 12) {
        int g = tid/3, d = tid - g*3;
        int p0 = (m0 & 32767) >> 5;
        s_cn[tid] = newxyz[(size_t)((b<<10) + p0 + g)*3 + d];
    }
    __syncthreads();
    for (int i = tid; i < 128*64; i += 256) {
        int r = i >> 6, cc = i & 63;
        AsT[(3 + cc)*ATS + r] = g_featT[((size_t)(b<<12) + s_j[r])*64 + cc];
    }
    for (int i = tid; i < 128*3; i += 256) {
        int r = i/3, d = i - r*3;
        AsT[d*ATS + r] = Xb[s_j[r]*3 + d] - s_cn[(r>>5)*3 + d];
    }
    __syncthreads();

    int tx = tid & 15, ty = tid >> 4;
    unsigned long long acc2[4][4];
#pragma unroll
    for (int p = 0; p < 4; p++)
#pragma unroll
        for (int v = 0; v < 4; v++) acc2[p][v] = 0ull;

    const unsigned long long* Ap =
        (const unsigned long long*)AsT + ty*4;          // row-pairs (ty*8+2p, +1)
    const float* Bc = g_Wt1 + tx*4;                     // global, L1-resident
    for (int k = 0; k < 67; k++) {
        unsigned long long a0 = Ap[k*(ATS/2) + 0];
        unsigned long long a1 = Ap[k*(ATS/2) + 1];
        unsigned long long a2 = Ap[k*(ATS/2) + 2];
        unsigned long long a3 = Ap[k*(ATS/2) + 3];
        float4 bv = *(const float4*)(Bc + k*64);
        unsigned long long d0 = dup2(bv.x), d1 = dup2(bv.y);
        unsigned long long d2 = dup2(bv.z), d3 = dup2(bv.w);
        ffma2(acc2[0][0], a0, d0); ffma2(acc2[0][1], a0, d1);
        ffma2(acc2[0][2], a0, d2); ffma2(acc2[0][3], a0, d3);
        ffma2(acc2[1][0], a1, d0); ffma2(acc2[1][1], a1, d1);
        ffma2(acc2[1][2], a1, d2); ffma2(acc2[1][3], a1, d3);
        ffma2(acc2[2][0], a2, d0); ffma2(acc2[2][1], a2, d1);
        ffma2(acc2[2][2], a2, d2); ffma2(acc2[2][3], a2, d3);
        ffma2(acc2[3][0], a3, d0); ffma2(acc2[3][1], a3, d1);
        ffma2(acc2[3][2], a3, d2); ffma2(acc2[3][3], a3, d3);
    }
    float acc[8][4];
#pragma unroll
    for (int p = 0; p < 4; p++)
#pragma unroll
        for (int v = 0; v < 4; v++) unpack2(acc2[p][v], acc[2*p][v], acc[2*p+1][v]);

    float ls[4] = {0,0,0,0}, lq[4] = {0,0,0,0};
#pragma unroll
    for (int u = 0; u < 8; u++) {
        float4 o = make_float4(acc[u][0], acc[u][1], acc[u][2], acc[u][3]);
        *(float4*)&g_x1[(size_t)(m0 + ty*8 + u)*64 + tx*4] = o;
#pragma unroll
        for (int v = 0; v < 4; v++) { ls[v] += acc[u][v]; lq[v] += acc[u][v]*acc[u][v]; }
    }
#pragma unroll
    for (int v = 0; v < 4; v++) {
        atomicAdd(&ssum[tx*4+v], (double)ls[v]);
        atomicAdd(&ssq [tx*4+v], (double)lq[v]);
    }
    __syncthreads();
    if (tid < 64) { atomicAdd(&g_s1[tid], ssum[tid]); atomicAdd(&g_q1[tid], ssq[tid]); }
}

// ---------------- stats: fold BN into scale/shift ----------------
__global__ void stats_kernel(int layer, const float* __restrict__ gg,
                             const float* __restrict__ bb) {
    int c = threadIdx.x;
    const double inv = 1.0 / (double)MT;
    if (layer == 1 && c < 64) {
        double m = g_s1[c]*inv, v = g_q1[c]*inv - m*m;
        float rs = rsqrtf((float)v + 1e-5f);
        float sc = gg[c]*rs;
        g_sc1[c] = sc; g_sh1[c] = bb[c] - (float)m*sc;
    } else if (layer == 2 && c < 64) {
        double m = g_s2[c]*inv, v = g_q2[c]*inv - m*m;
        float rs = rsqrtf((float)v + 1e-5f);
        float sc = gg[c]*rs;
        g_sc2[c] = sc; g_sh2[c] = bb[c] - (float)m*sc;
    } else if (layer == 3 && c < 128) {
        double m = g_s3[c]*inv, v = g_q3[c]*inv - m*m;
        float rs = rsqrtf((float)v + 1e-5f);
        float sc = gg[c]*rs;
        g_sc3[c] = sc; g_sh3[c] = bb[c] - (float)m*sc;
    }
}

// ---------------- GEMM2: relu(bn(x1)) @ W2^T -> x2, stats ----------------
__global__ __launch_bounds__(256) void gemm2_kernel() {
    extern __shared__ char smraw[];
    float*  AsT  = (float*)smraw;            // 64 x 130 (33280B, 8-al)
    double* ssum = (double*)(AsT + 64*ATS);  // 64 (byte 33280, 8-al)
    double* ssq  = ssum + 64;
    float*  s_sc = (float*)(ssq + 64);       // 64
    float*  s_sh = s_sc + 64;                // 64

    int tid = threadIdx.x;
    int m0 = blockIdx.x * 128;
    if (tid < 64) { ssum[tid]=0.0; ssq[tid]=0.0; s_sc[tid]=g_sc1[tid]; s_sh[tid]=g_sh1[tid]; }
    __syncthreads();
    for (int i = tid; i < 128*64; i += 256) {
        int r = i >> 6, cc = i & 63;
        float v = g_x1[(size_t)(m0 + r)*64 + cc];
        AsT[cc*ATS + r] = fmaxf(fmaf(v, s_sc[cc], s_sh[cc]), 0.f);
    }
    __syncthreads();

    int tx = tid & 15, ty = tid >> 4;
    unsigned long long acc2[4][4];
#pragma unroll
    for (int p = 0; p < 4; p++)
#pragma unroll
        for (int v = 0; v < 4; v++) acc2[p][v] = 0ull;

    const unsigned long long* Ap = (const unsigned long long*)AsT + ty*4;
    const float* Bc = g_Wt2 + tx*4;          // global, L1-resident
    for (int k = 0; k < 64; k++) {
        unsigned long long a0 = Ap[k*(ATS/2) + 0];
        unsigned long long a1 = Ap[k*(ATS/2) + 1];
        unsigned long long a2 = Ap[k*(ATS/2) + 2];
        unsigned long long a3 = Ap[k*(ATS/2) + 3];
        float4 bv = *(const float4*)(Bc + k*64);
        unsigned long long d0 = dup2(bv.x), d1 = dup2(bv.y);
        unsigned long long d2 = dup2(bv.z), d3 = dup2(bv.w);
        ffma2(acc2[0][0], a0, d0); ffma2(acc2[0][1], a0, d1);
        ffma2(acc2[0][2], a0, d2); ffma2(acc2[0][3], a0, d3);
        ffma2(acc2[1][0], a1, d0); ffma2(acc2[1][1], a1, d1);
        ffma2(acc2[1][2], a1, d2); ffma2(acc2[1][3], a1, d3);
        ffma2(acc2[2][0], a2, d0); ffma2(acc2[2][1], a2, d1);
        ffma2(acc2[2][2], a2, d2); ffma2(acc2[2][3], a2, d3);
        ffma2(acc2[3][0], a3, d0); ffma2(acc2[3][1], a3, d1);
        ffma2(acc2[3][2], a3, d2); ffma2(acc2[3][3], a3, d3);
    }
    float acc[8][4];
#pragma unroll
    for (int p = 0; p < 4; p++)
#pragma unroll
        for (int v = 0; v < 4; v++) unpack2(acc2[p][v], acc[2*p][v], acc[2*p+1][v]);

    float ls[4] = {0,0,0,0}, lq[4] = {0,0,0,0};
#pragma unroll
    for (int u = 0; u < 8; u++) {
        float4 o = make_float4(acc[u][0], acc[u][1], acc[u][2], acc[u][3]);
        *(float4*)&g_x2[(size_t)(m0 + ty*8 + u)*64 + tx*4] = o;
#pragma unroll
        for (int v = 0; v < 4; v++) { ls[v] += acc[u][v]; lq[v] += acc[u][v]*acc[u][v]; }
    }
#pragma unroll
    for (int v = 0; v < 4; v++) {
        atomicAdd(&ssum[tx*4+v], (double)ls[v]);
        atomicAdd(&ssq [tx*4+v], (double)lq[v]);
    }
    __syncthreads();
    if (tid < 64) { atomicAdd(&g_s2[tid], ssum[tid]); atomicAdd(&g_q2[tid], ssq[tid]); }
}

// ---------------- GEMM3: relu(bn(x2)) @ W3^T -> per-group max/min, stats ----------------
__global__ __launch_bounds__(256) void gemm3_kernel() {
    extern __shared__ char smraw[];
    float*    AsT  = (float*)smraw;               // 64 x 130 (33280B)
    double*   ssum = (double*)(AsT + 64*ATS);     // 128 (byte 33280, 8-al)
    double*   ssq  = ssum + 128;                  // 128
    unsigned* smax = (unsigned*)(ssq + 128);      // 4 x 128
    unsigned* smin = smax + 512;                  // 4 x 128
    float*    s_sc = (float*)(smin + 512);        // 64
    float*    s_sh = s_sc + 64;                   // 64
    // total: 33280 + 2048 + 4096 + 512 = 39936 bytes < 48KB

    int tid = threadIdx.x;
    int m0 = blockIdx.x * 128;
    if (tid < 128) { ssum[tid]=0.0; ssq[tid]=0.0; }
    if (tid < 64) { s_sc[tid]=g_sc2[tid]; s_sh[tid]=g_sh2[tid]; }
    for (int i = tid; i < 512; i += 256) { smax[i] = 0u; smin[i] = 0xffffffffu; }
    __syncthreads();
    for (int i = tid; i < 128*64; i += 256) {
        int r = i >> 6, cc = i & 63;
        float v = g_x2[(size_t)(m0 + r)*64 + cc];
        AsT[cc*ATS + r] = fmaxf(fmaf(v, s_sc[cc], s_sh[cc]), 0.f);
    }
    __syncthreads();

    int tx = tid & 15, ty = tid >> 4;
    unsigned long long acc2[4][8];
#pragma unroll
    for (int p = 0; p < 4; p++)
#pragma unroll
        for (int v = 0; v < 8; v++) acc2[p][v] = 0ull;

    const unsigned long long* Ap = (const unsigned long long*)AsT + ty*4;
    const float* Bc = g_Wt3 + tx*8;               // global, L1-resident
    for (int k = 0; k < 64; k++) {
        unsigned long long a0 = Ap[k*(ATS/2) + 0];
        unsigned long long a1 = Ap[k*(ATS/2) + 1];
        unsigned long long a2 = Ap[k*(ATS/2) + 2];
        unsigned long long a3 = Ap[k*(ATS/2) + 3];
        float4 b0 = *(const float4*)(Bc + k*128);
        float4 b1 = *(const float4*)(Bc + k*128 + 4);
        unsigned long long d0 = dup2(b0.x), d1 = dup2(b0.y);
        unsigned long long d2 = dup2(b0.z), d3 = dup2(b0.w);
        unsigned long long d4 = dup2(b1.x), d5 = dup2(b1.y);
        unsigned long long d6 = dup2(b1.z), d7 = dup2(b1.w);
        ffma2(acc2[0][0], a0, d0); ffma2(acc2[0][1], a0, d1);
        ffma2(acc2[0][2], a0, d2); ffma2(acc2[0][3], a0, d3);
        ffma2(acc2[0][4], a0, d4); ffma2(acc2[0][5], a0, d5);
        ffma2(acc2[0][6], a0, d6); ffma2(acc2[0][7], a0, d7);
        ffma2(acc2[1][0], a1, d0); ffma2(acc2[1][1], a1, d1);
        ffma2(acc2[1][2], a1, d2); ffma2(acc2[1][3], a1, d3);
        ffma2(acc2[1][4], a1, d4); ffma2(acc2[1][5], a1, d5);
        ffma2(acc2[1][6], a1, d6); ffma2(acc2[1][7], a1, d7);
        ffma2(acc2[2][0], a2, d0); ffma2(acc2[2][1], a2, d1);
        ffma2(acc2[2][2], a2, d2); ffma2(acc2[2][3], a2, d3);
        ffma2(acc2[2][4], a2, d4); ffma2(acc2[2][5], a2, d5);
        ffma2(acc2[2][6], a2, d6); ffma2(acc2[2][7], a2, d7);
        ffma2(acc2[3][0], a3, d0); ffma2(acc2[3][1], a3, d1);
        ffma2(acc2[3][2], a3, d2); ffma2(acc2[3][3], a3, d3);
        ffma2(acc2[3][4], a3, d4); ffma2(acc2[3][5], a3, d5);
        ffma2(acc2[3][6], a3, d6); ffma2(acc2[3][7], a3, d7);
    }
    float acc[8][8];
#pragma unroll
    for (int p = 0; p < 4; p++)
#pragma unroll
        for (int v = 0; v < 8; v++) unpack2(acc2[p][v], acc[2*p][v], acc[2*p+1][v]);

    int g = ty >> 2;  // all 8 rows of this thread are in s-group g
    float ls[8], lq[8], mx[8], mn[8];
#pragma unroll
    for (int v = 0; v < 8; v++) { ls[v]=0.f; lq[v]=0.f; mx[v]=-3.4e38f; mn[v]=3.4e38f; }
#pragma unroll
    for (int u = 0; u < 8; u++)
#pragma unroll
        for (int v = 0; v < 8; v++) {
            float a = acc[u][v];
            ls[v] += a; lq[v] += a*a;
            mx[v] = fmaxf(mx[v], a); mn[v] = fminf(mn[v], a);
        }
#pragma unroll
    for (int v = 0; v < 8; v++) {
        int c = tx*8 + v;
        atomicAdd(&ssum[c], (double)ls[v]);
        atomicAdd(&ssq [c], (double)lq[v]);
        atomicMax(&smax[g*128 + c], fenc(mx[v]));
        atomicMin(&smin[g*128 + c], fenc(mn[v]));
    }
    __syncthreads();
    if (tid < 128) { atomicAdd(&g_s3[tid], ssum[tid]); atomicAdd(&g_q3[tid], ssq[tid]); }
    for (int i = tid; i < 512; i += 256) {
        int gg = i >> 7, c = i & 127;
        size_t idx = (size_t)(blockIdx.x*4 + gg)*128 + c;
        g_mx[idx] = fdec(smax[i]);
        g_mn[idx] = fdec(smin[i]);
    }
}

// ---------------- final: bn3+relu on max/min, transposed write ----------------
__global__ void final_kernel(float* __restrict__ out) {
    __shared__ float tile[32][33];
    int b = blockIdx.z, pT = blockIdx.x*32, cT = blockIdx.y*32;
    int tx = threadIdx.x, ty = threadIdx.y;
    int c = cT + tx;
    float sc = g_sc3[c], sh = g_sh3[c];
    for (int r = ty; r < 32; r += 8) {
        int p = pT + r;
        size_t idx = (size_t)((b<<10) + p)*128 + c;
        float v = (sc >= 0.f) ? g_mx[idx] : g_mn[idx];
        tile[r][tx] = fmaxf(fmaf(v, sc, sh), 0.f);
    }
    __syncthreads();
    int p = pT + tx;
    for (int r = ty; r < 32; r += 8) {
        int c2 = cT + r;
        out[OUT_FEAT_OFF + (size_t)b*131072 + (size_t)c2*1024 + p] = tile[tx][r];
    }
}

// ---------------- launcher (kernel launches ONLY — graph-capture safe) ----------------
extern "C" void kernel_launch(void* const* d_in, const int* in_sizes, int n_in,
                              void* d_out, int out_size) {
    const float* xyz      = (const float*)d_in[0];
    const float* features = (const float*)d_in[1];
    const float* W1 = (const float*)d_in[2];
    const float* g1 = (const float*)d_in[3];
    const float* b1 = (const float*)d_in[4];
    const float* W2 = (const float*)d_in[5];
    const float* g2 = (const float*)d_in[6];
    const float* b2 = (const float*)d_in[7];
    const float* W3 = (const float*)d_in[8];
    const float* g3 = (const float*)d_in[9];
    const float* b3 = (const float*)d_in[10];
    float* out = (float*)d_out;

    // dynamic shared sizes — all well under the 48KB default cap
    size_t sh1 = (67*ATS + 2)*4 + 64*2*8 + 128*4 + 12*4 + 64;  // ~36.4KB
    size_t sh2 = (64*ATS)*4 + 64*2*8 + 64*2*4 + 64;            // ~34.4KB
    size_t sh3 = (64*ATS)*4 + 128*2*8 + 1024*4 + 128*4 + 64;   // ~40.0KB

    prep_kernel<<<1, 256>>>(W1, W2, W3);
    featT_kernel<<<dim3(NN/32, NC/32, NB), dim3(32, 8)>>>(features);
    fps_kernel<<<NB, 1024>>>(xyz, out);
    ball_kernel<<<(NB*NP)/8, 256>>>(xyz, out);
    gemm1_kernel<<<MT/128, 256, sh1>>>(xyz, out);
    stats_kernel<<<1, 128>>>(1, g1, b1);
    gemm2_kernel<<<MT/128, 256, sh2>>>();
    stats_kernel<<<1, 128>>>(2, g2, b2);
    gemm3_kernel<<<MT/128, 256, sh3>>>();
    stats_kernel<<<1, 128>>>(3, g3, b3);
    final_kernel<<<dim3(NP/32, 128/32, NB), dim3(32, 8)>>>(out);
}

// round 11
// speedup vs baseline: 1.1560x; 1.1560x over previous
#include <cuda_runtime.h>
#include <cstdint>

#define NB 16
#define NN 4096
#define NC 64
#define NP 1024
#define NSAMP 32
#define MT (NB*NP*NSAMP)          // 524288 rows
#define OUT_FEAT_OFF (NB*NP*3)    // 49152

// ---------------- scratch (__device__ globals; no allocations) ----------------
__device__ __align__(16) float  g_featT[NB*NN*NC];   // (B,N,C) features, 16.8MB
__device__             int      g_ball[NB*NP*NSAMP]; // ball query indices
__device__ __align__(16) float  g_x1[MT*64];         // raw layer1 out, 134MB
__device__ __align__(16) float  g_x2[MT*64];         // raw layer2 out, 134MB
__device__ __align__(16) float  g_mx[NB*NP*128];     // raw layer3 max over s
__device__ __align__(16) float  g_mn[NB*NP*128];     // raw layer3 min over s
__device__ __align__(16) float  g_Wt1[67*64];
__device__ __align__(16) float  g_Wt2[64*64];
__device__ __align__(16) float  g_Wt3[64*128];
__device__ double g_s1[64], g_q1[64], g_s2[64], g_q2[64], g_s3[128], g_q3[128];
__device__ float  g_sc1[64], g_sh1[64], g_sc2[64], g_sh2[64], g_sc3[128], g_sh3[128];

// monotonic float<->uint encoding (for atomic max/min on possibly-negative floats)
__device__ __forceinline__ unsigned fenc(float f) {
    unsigned u = __float_as_uint(f);
    return (u & 0x80000000u) ? ~u : (u | 0x80000000u);
}
__device__ __forceinline__ float fdec(unsigned u) {
    u = (u & 0x80000000u) ? (u & 0x7fffffffu) : ~u;
    return __uint_as_float(u);
}

// squared distance with NO fma contraction, left-associated like XLA:
// (dx*dx + dy*dy) + dz*dz
__device__ __forceinline__ float dist2_xla(float dx, float dy, float dz) {
    return __fadd_rn(__fadd_rn(__fmul_rn(dx, dx), __fmul_rn(dy, dy)),
                     __fmul_rn(dz, dz));
}

// ---------------- packed f32x2 helpers (FFMA2 path, sm_103a) ----------------
__device__ __forceinline__ void ffma2(unsigned long long& d,
                                      unsigned long long a,
                                      unsigned long long b) {
    asm("fma.rn.f32x2 %0, %1, %2, %0;" : "+l"(d) : "l"(a), "l"(b));
}
__device__ __forceinline__ unsigned long long dup2(float x) {
    unsigned u = __float_as_uint(x);
    unsigned long long r;
    asm("mov.b64 %0, {%1, %1};" : "=l"(r) : "r"(u));
    return r;
}
__device__ __forceinline__ void unpack2(unsigned long long v, float& lo, float& hi) {
    unsigned a, b;
    asm("mov.b64 {%0, %1}, %2;" : "=r"(a), "=r"(b) : "l"(v));
    lo = __uint_as_float(a); hi = __uint_as_float(b);
}

// ---------------- prep: zero accumulators + transpose weights ----------------
__global__ void prep_kernel(const float* __restrict__ W1,
                            const float* __restrict__ W2,
                            const float* __restrict__ W3) {
    int t = threadIdx.x;
    for (int i = t; i < 64; i += 256) { g_s1[i]=0.0; g_q1[i]=0.0; g_s2[i]=0.0; g_q2[i]=0.0; }
    for (int i = t; i < 128; i += 256) { g_s3[i]=0.0; g_q3[i]=0.0; }
    for (int i = t; i < 64*67; i += 256) { int o = i/67, c = i - o*67; g_Wt1[c*64 + o] = W1[i]; }
    for (int i = t; i < 64*64; i += 256) { int o = i>>6, c = i&63;    g_Wt2[c*64 + o] = W2[i]; }
    for (int i = t; i < 128*64; i += 256){ int o = i>>6, c = i&63;    g_Wt3[c*128 + o] = W3[i]; }
}

// ---------------- transpose features (B,C,N) -> (B,N,C) ----------------
__global__ void featT_kernel(const float* __restrict__ f) {
    __shared__ float t[32][33];
    int b = blockIdx.z, j0 = blockIdx.x*32, c0 = blockIdx.y*32;
    int tx = threadIdx.x, ty = threadIdx.y;
    for (int k = ty; k < 32; k += 8)
        t[k][tx] = f[b*(NC*NN) + (c0+k)*NN + j0 + tx];
    __syncthreads();
    for (int k = ty; k < 32; k += 8)
        g_featT[(b*NN + j0 + k)*NC + c0 + tx] = t[tx][k];
}

// ---------------- FPS: one block per batch, ONE barrier per iteration --------
// NO shared atomics (ATOMS to one address serializes 32cyc/warp -> ~1024cy/iter
// with 32 warps; measured R9 total implies fps ~1.1ms from exactly this).
// Two-level REDUX instead:
//   stage 1: per-warp (maxdist, min idx) via 2x __reduce_max_sync
//   stage 2: lane0 stores packed u64 to s_warp[i&1][wid]; after ONE barrier,
//            EVERY warp redundantly reduces the 32 per-warp values with 2 more
//            REDUX ops. Double buffer (i&1) kills the fast-writer race; all 32
//            slots are rewritten every iteration so no clears are needed.
// Tie-break identical to packed-u64 atomicMax: max dist, then min index.
__global__ __launch_bounds__(1024) void fps_kernel(const float* __restrict__ xyz,
                                                   float* __restrict__ out) {
    __shared__ unsigned long long s_warp[2][32];

    int b = blockIdx.x, tid = threadIdx.x;
    int lane = tid & 31, wid = tid >> 5;
    const float* X = xyz + b*NN*3;

    float px[4], py[4], pz[4], dist[4];
#pragma unroll
    for (int k = 0; k < 4; k++) {
        int j = tid + k*1024;
        px[k] = X[j*3+0]; py[k] = X[j*3+1]; pz[k] = X[j*3+2];
        dist[k] = 1e10f;
    }

    int cur = 0;
    float* outB = out + b*NP*3;
    for (int i = 0; i < NP; i++) {
        // broadcast read of current point's coords (all lanes same address, L1)
        float lx = __ldg(&X[cur*3+0]);
        float ly = __ldg(&X[cur*3+1]);
        float lz = __ldg(&X[cur*3+2]);
        if (tid == 0) { outB[i*3+0] = lx; outB[i*3+1] = ly; outB[i*3+2] = lz; }

        // thread-local best among 4 points (max dist, then lowest index)
        unsigned long long best = 0ull;
#pragma unroll
        for (int k = 0; k < 4; k++) {
            float d = dist2_xla(px[k]-lx, py[k]-ly, pz[k]-lz);
            d = fminf(dist[k], d);
            dist[k] = d;
            unsigned long long key =
                (((unsigned long long)__float_as_uint(d)) << 32) |
                (unsigned)(4095 - (tid + k*1024));
            best = (key > best) ? key : best;
        }
        // stage 1: warp winner via two u32 REDUX ops
        unsigned d32  = (unsigned)(best >> 32);
        unsigned m    = __reduce_max_sync(0xffffffffu, d32);
        unsigned ridx = (d32 == m) ? (unsigned)(best & 0xffffffffu) : 0u;
        unsigned rmax = __reduce_max_sync(0xffffffffu, ridx);
        if (lane == 0)
            s_warp[i & 1][wid] = (((unsigned long long)m) << 32) | rmax;
        __syncthreads();

        // stage 2: every warp redundantly reduces the 32 per-warp winners
        unsigned long long wv = s_warp[i & 1][lane];
        unsigned wd = (unsigned)(wv >> 32);
        unsigned m2 = __reduce_max_sync(0xffffffffu, wd);
        unsigned c2 = (wd == m2) ? (unsigned)(wv & 0xffffffffu) : 0u;
        unsigned r2 = __reduce_max_sync(0xffffffffu, c2);
        cur = 4095 - (int)r2;
    }
}

// ---------------- ball query: warp per center ----------------
__global__ __launch_bounds__(256) void ball_kernel(const float* __restrict__ xyz,
                                                   const float* __restrict__ newxyz) {
    int w = blockIdx.x*8 + (threadIdx.x >> 5);
    int lane = threadIdx.x & 31;
    int b = w >> 10, p = w & 1023;
    const float* X = xyz + b*NN*3;
    const float* c = newxyz + (size_t)(b*NP + p)*3;
    float cx = c[0], cy = c[1], cz = c[2];
    int* dst = g_ball + (size_t)(b*NP + p)*NSAMP;
    const float RR = 0.04f;   // float32(0.2*0.2)

    int cnt = 0, first = -1;
    for (int j0 = 0; j0 < NN && cnt < NSAMP; j0 += 32) {
        int j = j0 + lane;
        float d = dist2_xla(X[j*3+0]-cx, X[j*3+1]-cy, X[j*3+2]-cz);
        bool val = d < RR;
        unsigned m = __ballot_sync(0xffffffffu, val);
        if (m) {
            if (first < 0) first = __shfl_sync(0xffffffffu, j, __ffs(m)-1);
            if (val) {
                int pos = cnt + __popc(m & ((1u << lane) - 1u));
                if (pos < NSAMP) dst[pos] = j;
            }
            cnt += __popc(m);
            if (cnt > NSAMP) cnt = NSAMP;
        }
    }
    if (lane >= cnt) dst[lane] = first;
}

// A tile is stored K-major: As_T[k*130 + r], r = 0..127, k = channel.
// Stride 130 (even) keeps 8B alignment for ld.shared.b64 row-pair loads.
// B (weights) read straight from L1-resident __device__ globals.
#define ATS 130

// ---------------- GEMM1: gather + (B,P,S,67) @ W1^T -> x1, stats ----------------
__global__ __launch_bounds__(256) void gemm1_kernel(const float* __restrict__ xyz,
                                                    const float* __restrict__ newxyz) {
    extern __shared__ char smraw[];
    float*  AsT  = (float*)smraw;                       // 67 x 130 (+2 pad)
    double* ssum = (double*)(AsT + 67*ATS + 2);         // 64 (byte 34848, 8-al)
    double* ssq  = ssum + 64;                           // 64
    int*    s_j  = (int*)(ssq + 64);                    // 128
    float*  s_cn = (float*)(s_j + 128);                 // 12

    int tid = threadIdx.x;
    int m0 = blockIdx.x * 128;
    int b  = m0 >> 15;
    const float* Xb = xyz + b*NN*3;

    if (tid < 64) { ssum[tid] = 0.0; ssq[tid] = 0.0; }
    for (int r = tid; r < 128; r += 256) {
        int m = m0 + r; int p = (m & 32767) >> 5; int s = m & 31;
        s_j[r] = g_ball[(((b<<10) + p) << 5) + s];
    }
    if (tid < 12) {
        int g = tid/3, d = tid - g*3;
        int p0 = (m0 & 32767) >> 5;
        s_cn[tid] = newxyz[(size_t)((b<<10) + p0 + g)*3 + d];
    }
    __syncthreads();
    for (int i = tid; i < 128*64; i += 256) {
        int r = i >> 6, cc = i & 63;
        AsT[(3 + cc)*ATS + r] = g_featT[((size_t)(b<<12) + s_j[r])*64 + cc];
    }
    for (int i = tid; i < 128*3; i += 256) {
        int r = i/3, d = i - r*3;
        AsT[d*ATS + r] = Xb[s_j[r]*3 + d] - s_cn[(r>>5)*3 + d];
    }
    __syncthreads();

    int tx = tid & 15, ty = tid >> 4;
    unsigned long long acc2[4][4];
#pragma unroll
    for (int p = 0; p < 4; p++)
#pragma unroll
        for (int v = 0; v < 4; v++) acc2[p][v] = 0ull;

    const unsigned long long* Ap =
        (const unsigned long long*)AsT + ty*4;          // row-pairs (ty*8+2p, +1)
    const float* Bc = g_Wt1 + tx*4;                     // global, L1-resident
    for (int k = 0; k < 67; k++) {
        unsigned long long a0 = Ap[k*(ATS/2) + 0];
        unsigned long long a1 = Ap[k*(ATS/2) + 1];
        unsigned long long a2 = Ap[k*(ATS/2) + 2];
        unsigned long long a3 = Ap[k*(ATS/2) + 3];
        float4 bv = *(const float4*)(Bc + k*64);
        unsigned long long d0 = dup2(bv.x), d1 = dup2(bv.y);
        unsigned long long d2 = dup2(bv.z), d3 = dup2(bv.w);
        ffma2(acc2[0][0], a0, d0); ffma2(acc2[0][1], a0, d1);
        ffma2(acc2[0][2], a0, d2); ffma2(acc2[0][3], a0, d3);
        ffma2(acc2[1][0], a1, d0); ffma2(acc2[1][1], a1, d1);
        ffma2(acc2[1][2], a1, d2); ffma2(acc2[1][3], a1, d3);
        ffma2(acc2[2][0], a2, d0); ffma2(acc2[2][1], a2, d1);
        ffma2(acc2[2][2], a2, d2); ffma2(acc2[2][3], a2, d3);
        ffma2(acc2[3][0], a3, d0); ffma2(acc2[3][1], a3, d1);
        ffma2(acc2[3][2], a3, d2); ffma2(acc2[3][3], a3, d3);
    }
    float acc[8][4];
#pragma unroll
    for (int p = 0; p < 4; p++)
#pragma unroll
        for (int v = 0; v < 4; v++) unpack2(acc2[p][v], acc[2*p][v], acc[2*p+1][v]);

    float ls[4] = {0,0,0,0}, lq[4] = {0,0,0,0};
#pragma unroll
    for (int u = 0; u < 8; u++) {
        float4 o = make_float4(acc[u][0], acc[u][1], acc[u][2], acc[u][3]);
        *(float4*)&g_x1[(size_t)(m0 + ty*8 + u)*64 + tx*4] = o;
#pragma unroll
        for (int v = 0; v < 4; v++) { ls[v] += acc[u][v]; lq[v] += acc[u][v]*acc[u][v]; }
    }
#pragma unroll
    for (int v = 0; v < 4; v++) {
        atomicAdd(&ssum[tx*4+v], (double)ls[v]);
        atomicAdd(&ssq [tx*4+v], (double)lq[v]);
    }
    __syncthreads();
    if (tid < 64) { atomicAdd(&g_s1[tid], ssum[tid]); atomicAdd(&g_q1[tid], ssq[tid]); }
}

// ---------------- stats: fold BN into scale/shift ----------------
__global__ void stats_kernel(int layer, const float* __restrict__ gg,
                             const float* __restrict__ bb) {
    int c = threadIdx.x;
    const double inv = 1.0 / (double)MT;
    if (layer == 1 && c < 64) {
        double m = g_s1[c]*inv, v = g_q1[c]*inv - m*m;
        float rs = rsqrtf((float)v + 1e-5f);
        float sc = gg[c]*rs;
        g_sc1[c] = sc; g_sh1[c] = bb[c] - (float)m*sc;
    } else if (layer == 2 && c < 64) {
        double m = g_s2[c]*inv, v = g_q2[c]*inv - m*m;
        float rs = rsqrtf((float)v + 1e-5f);
        float sc = gg[c]*rs;
        g_sc2[c] = sc; g_sh2[c] = bb[c] - (float)m*sc;
    } else if (layer == 3 && c < 128) {
        double m = g_s3[c]*inv, v = g_q3[c]*inv - m*m;
        float rs = rsqrtf((float)v + 1e-5f);
        float sc = gg[c]*rs;
        g_sc3[c] = sc; g_sh3[c] = bb[c] - (float)m*sc;
    }
}

// ---------------- GEMM2: relu(bn(x1)) @ W2^T -> x2, stats ----------------
__global__ __launch_bounds__(256) void gemm2_kernel() {
    extern __shared__ char smraw[];
    float*  AsT  = (float*)smraw;            // 64 x 130 (33280B, 8-al)
    double* ssum = (double*)(AsT + 64*ATS);  // 64 (byte 33280, 8-al)
    double* ssq  = ssum + 64;
    float*  s_sc = (float*)(ssq + 64);       // 64
    float*  s_sh = s_sc + 64;                // 64

    int tid = threadIdx.x;
    int m0 = blockIdx.x * 128;
    if (tid < 64) { ssum[tid]=0.0; ssq[tid]=0.0; s_sc[tid]=g_sc1[tid]; s_sh[tid]=g_sh1[tid]; }
    __syncthreads();
    for (int i = tid; i < 128*64; i += 256) {
        int r = i >> 6, cc = i & 63;
        float v = g_x1[(size_t)(m0 + r)*64 + cc];
        AsT[cc*ATS + r] = fmaxf(fmaf(v, s_sc[cc], s_sh[cc]), 0.f);
    }
    __syncthreads();

    int tx = tid & 15, ty = tid >> 4;
    unsigned long long acc2[4][4];
#pragma unroll
    for (int p = 0; p < 4; p++)
#pragma unroll
        for (int v = 0; v < 4; v++) acc2[p][v] = 0ull;

    const unsigned long long* Ap = (const unsigned long long*)AsT + ty*4;
    const float* Bc = g_Wt2 + tx*4;          // global, L1-resident
    for (int k = 0; k < 64; k++) {
        unsigned long long a0 = Ap[k*(ATS/2) + 0];
        unsigned long long a1 = Ap[k*(ATS/2) + 1];
        unsigned long long a2 = Ap[k*(ATS/2) + 2];
        unsigned long long a3 = Ap[k*(ATS/2) + 3];
        float4 bv = *(const float4*)(Bc + k*64);
        unsigned long long d0 = dup2(bv.x), d1 = dup2(bv.y);
        unsigned long long d2 = dup2(bv.z), d3 = dup2(bv.w);
        ffma2(acc2[0][0], a0, d0); ffma2(acc2[0][1], a0, d1);
        ffma2(acc2[0][2], a0, d2); ffma2(acc2[0][3], a0, d3);
        ffma2(acc2[1][0], a1, d0); ffma2(acc2[1][1], a1, d1);
        ffma2(acc2[1][2], a1, d2); ffma2(acc2[1][3], a1, d3);
        ffma2(acc2[2][0], a2, d0); ffma2(acc2[2][1], a2, d1);
        ffma2(acc2[2][2], a2, d2); ffma2(acc2[2][3], a2, d3);
        ffma2(acc2[3][0], a3, d0); ffma2(acc2[3][1], a3, d1);
        ffma2(acc2[3][2], a3, d2); ffma2(acc2[3][3], a3, d3);
    }
    float acc[8][4];
#pragma unroll
    for (int p = 0; p < 4; p++)
#pragma unroll
        for (int v = 0; v < 4; v++) unpack2(acc2[p][v], acc[2*p][v], acc[2*p+1][v]);

    float ls[4] = {0,0,0,0}, lq[4] = {0,0,0,0};
#pragma unroll
    for (int u = 0; u < 8; u++) {
        float4 o = make_float4(acc[u][0], acc[u][1], acc[u][2], acc[u][3]);
        *(float4*)&g_x2[(size_t)(m0 + ty*8 + u)*64 + tx*4] = o;
#pragma unroll
        for (int v = 0; v < 4; v++) { ls[v] += acc[u][v]; lq[v] += acc[u][v]*acc[u][v]; }
    }
#pragma unroll
    for (int v = 0; v < 4; v++) {
        atomicAdd(&ssum[tx*4+v], (double)ls[v]);
        atomicAdd(&ssq [tx*4+v], (double)lq[v]);
    }
    __syncthreads();
    if (tid < 64) { atomicAdd(&g_s2[tid], ssum[tid]); atomicAdd(&g_q2[tid], ssq[tid]); }
}

// ---------------- GEMM3: relu(bn(x2)) @ W3^T -> per-group max/min, stats ----------------
__global__ __launch_bounds__(256) void gemm3_kernel() {
    extern __shared__ char smraw[];
    float*    AsT  = (float*)smraw;               // 64 x 130 (33280B)
    double*   ssum = (double*)(AsT + 64*ATS);     // 128 (byte 33280, 8-al)
    double*   ssq  = ssum + 128;                  // 128
    unsigned* smax = (unsigned*)(ssq + 128);      // 4 x 128
    unsigned* smin = smax + 512;                  // 4 x 128
    float*    s_sc = (float*)(smin + 512);        // 64
    float*    s_sh = s_sc + 64;                   // 64
    // total: 33280 + 2048 + 4096 + 512 = 39936 bytes < 48KB

    int tid = threadIdx.x;
    int m0 = blockIdx.x * 128;
    if (tid < 128) { ssum[tid]=0.0; ssq[tid]=0.0; }
    if (tid < 64) { s_sc[tid]=g_sc2[tid]; s_sh[tid]=g_sh2[tid]; }
    for (int i = tid; i < 512; i += 256) { smax[i] = 0u; smin[i] = 0xffffffffu; }
    __syncthreads();
    for (int i = tid; i < 128*64; i += 256) {
        int r = i >> 6, cc = i & 63;
        float v = g_x2[(size_t)(m0 + r)*64 + cc];
        AsT[cc*ATS + r] = fmaxf(fmaf(v, s_sc[cc], s_sh[cc]), 0.f);
    }
    __syncthreads();

    int tx = tid & 15, ty = tid >> 4;
    unsigned long long acc2[4][8];
#pragma unroll
    for (int p = 0; p < 4; p++)
#pragma unroll
        for (int v = 0; v < 8; v++) acc2[p][v] = 0ull;

    const unsigned long long* Ap = (const unsigned long long*)AsT + ty*4;
    const float* Bc = g_Wt3 + tx*8;               // global, L1-resident
    for (int k = 0; k < 64; k++) {
        unsigned long long a0 = Ap[k*(ATS/2) + 0];
        unsigned long long a1 = Ap[k*(ATS/2) + 1];
        unsigned long long a2 = Ap[k*(ATS/2) + 2];
        unsigned long long a3 = Ap[k*(ATS/2) + 3];
        float4 b0 = *(const float4*)(Bc + k*128);
        float4 b1 = *(const float4*)(Bc + k*128 + 4);
        unsigned long long d0 = dup2(b0.x), d1 = dup2(b0.y);
        unsigned long long d2 = dup2(b0.z), d3 = dup2(b0.w);
        unsigned long long d4 = dup2(b1.x), d5 = dup2(b1.y);
        unsigned long long d6 = dup2(b1.z), d7 = dup2(b1.w);
        ffma2(acc2[0][0], a0, d0); ffma2(acc2[0][1], a0, d1);
        ffma2(acc2[0][2], a0, d2); ffma2(acc2[0][3], a0, d3);
        ffma2(acc2[0][4], a0, d4); ffma2(acc2[0][5], a0, d5);
        ffma2(acc2[0][6], a0, d6); ffma2(acc2[0][7], a0, d7);
        ffma2(acc2[1][0], a1, d0); ffma2(acc2[1][1], a1, d1);
        ffma2(acc2[1][2], a1, d2); ffma2(acc2[1][3], a1, d3);
        ffma2(acc2[1][4], a1, d4); ffma2(acc2[1][5], a1, d5);
        ffma2(acc2[1][6], a1, d6); ffma2(acc2[1][7], a1, d7);
        ffma2(acc2[2][0], a2, d0); ffma2(acc2[2][1], a2, d1);
        ffma2(acc2[2][2], a2, d2); ffma2(acc2[2][3], a2, d3);
        ffma2(acc2[2][4], a2, d4); ffma2(acc2[2][5], a2, d5);
        ffma2(acc2[2][6], a2, d6); ffma2(acc2[2][7], a2, d7);
        ffma2(acc2[3][0], a3, d0); ffma2(acc2[3][1], a3, d1);
        ffma2(acc2[3][2], a3, d2); ffma2(acc2[3][3], a3, d3);
        ffma2(acc2[3][4], a3, d4); ffma2(acc2[3][5], a3, d5);
        ffma2(acc2[3][6], a3, d6); ffma2(acc2[3][7], a3, d7);
    }
    float acc[8][8];
#pragma unroll
    for (int p = 0; p < 4; p++)
#pragma unroll
        for (int v = 0; v < 8; v++) unpack2(acc2[p][v], acc[2*p][v], acc[2*p+1][v]);

    int g = ty >> 2;  // all 8 rows of this thread are in s-group g
    float ls[8], lq[8], mx[8], mn[8];
#pragma unroll
    for (int v = 0; v < 8; v++) { ls[v]=0.f; lq[v]=0.f; mx[v]=-3.4e38f; mn[v]=3.4e38f; }
#pragma unroll
    for (int u = 0; u < 8; u++)
#pragma unroll
        for (int v = 0; v < 8; v++) {
            float a = acc[u][v];
            ls[v] += a; lq[v] += a*a;
            mx[v] = fmaxf(mx[v], a); mn[v] = fminf(mn[v], a);
        }
#pragma unroll
    for (int v = 0; v < 8; v++) {
        int c = tx*8 + v;
        atomicAdd(&ssum[c], (double)ls[v]);
        atomicAdd(&ssq [c], (double)lq[v]);
        atomicMax(&smax[g*128 + c], fenc(mx[v]));
        atomicMin(&smin[g*128 + c], fenc(mn[v]));
    }
    __syncthreads();
    if (tid < 128) { atomicAdd(&g_s3[tid], ssum[tid]); atomicAdd(&g_q3[tid], ssq[tid]); }
    for (int i = tid; i < 512; i += 256) {
        int gg = i >> 7, c = i & 127;
        size_t idx = (size_t)(blockIdx.x*4 + gg)*128 + c;
        g_mx[idx] = fdec(smax[i]);
        g_mn[idx] = fdec(smin[i]);
    }
}

// ---------------- final: bn3+relu on max/min, transposed write ----------------
__global__ void final_kernel(float* __restrict__ out) {
    __shared__ float tile[32][33];
    int b = blockIdx.z, pT = blockIdx.x*32, cT = blockIdx.y*32;
    int tx = threadIdx.x, ty = threadIdx.y;
    int c = cT + tx;
    float sc = g_sc3[c], sh = g_sh3[c];
    for (int r = ty; r < 32; r += 8) {
        int p = pT + r;
        size_t idx = (size_t)((b<<10) + p)*128 + c;
        float v = (sc >= 0.f) ? g_mx[idx] : g_mn[idx];
        tile[r][tx] = fmaxf(fmaf(v, sc, sh), 0.f);
    }
    __syncthreads();
    int p = pT + tx;
    for (int r = ty; r < 32; r += 8) {
        int c2 = cT + r;
        out[OUT_FEAT_OFF + (size_t)b*131072 + (size_t)c2*1024 + p] = tile[tx][r];
    }
}

// ---------------- launcher (kernel launches ONLY — graph-capture safe) ----------------
extern "C" void kernel_launch(void* const* d_in, const int* in_sizes, int n_in,
                              void* d_out, int out_size) {
    const float* xyz      = (const float*)d_in[0];
    const float* features = (const float*)d_in[1];
    const float* W1 = (const float*)d_in[2];
    const float* g1 = (const float*)d_in[3];
    const float* b1 = (const float*)d_in[4];
    const float* W2 = (const float*)d_in[5];
    const float* g2 = (const float*)d_in[6];
    const float* b2 = (const float*)d_in[7];
    const float* W3 = (const float*)d_in[8];
    const float* g3 = (const float*)d_in[9];
    const float* b3 = (const float*)d_in[10];
    float* out = (float*)d_out;

    // dynamic shared sizes — all well under the 48KB default cap
    size_t sh1 = (67*ATS + 2)*4 + 64*2*8 + 128*4 + 12*4 + 64;  // ~36.4KB
    size_t sh2 = (64*ATS)*4 + 64*2*8 + 64*2*4 + 64;            // ~34.4KB
    size_t sh3 = (64*ATS)*4 + 128*2*8 + 1024*4 + 128*4 + 64;   // ~40.0KB

    prep_kernel<<<1, 256>>>(W1, W2, W3);
    featT_kernel<<<dim3(NN/32, NC/32, NB), dim3(32, 8)>>>(features);
    fps_kernel<<<NB, 1024>>>(xyz, out);
    ball_kernel<<<(NB*NP)/8, 256>>>(xyz, out);
    gemm1_kernel<<<MT/128, 256, sh1>>>(xyz, out);
    stats_kernel<<<1, 128>>>(1, g1, b1);
    gemm2_kernel<<<MT/128, 256, sh2>>>();
    stats_kernel<<<1, 128>>>(2, g2, b2);
    gemm3_kernel<<<MT/128, 256, sh3>>>();
    stats_kernel<<<1, 128>>>(3, g3, b3);
    final_kernel<<<dim3(NP/32, 128/32, NB), dim3(32, 8)>>>(out);
}